// round 15
// baseline (speedup 1.0000x reference)
#include <cuda_runtime.h>
#include <cuda_bf16.h>
#include <cstdint>

// ---------------- constants ----------------
#define BSZ 2
#define LSEQ 4097            // 1 + 4*1024
#define DM 256               // D_MODEL
#define DIM 512
#define DIN 512              // D_INNER
#define DST 16               // D_STATE
#define DTR 16               // DT_RANK
#define NROWS (BSZ*LSEQ)     // 8194
#define NCH 65               // ceil(4097/64)
#define CHUNK 64
#define NSER (BSZ*DIN*DST)   // 16384 scan series
#define EPSV 1e-5f

// ---------------- scratch (device globals; no runtime alloc) ----------------
__device__ __align__(16) float g_e[2048 * 1024];           // expand GEMM output
__device__ __align__(16) float g_u[NROWS * DM];            // layer ping
__device__ __align__(16) float g_u2[NROWS * DM];           // layer pong
__device__ __align__(16) float g_xz[NROWS * 1024];         // in_proj output (xi | z)
__device__ __align__(16) float g_xc[NROWS * DIN];          // conv+silu output
__device__ __align__(16) float g_dbc[NROWS * 48];          // dt|B|C
__device__ __align__(16) float g_delta[NROWS * DIN];       // softplus(dt@Wdt+b)
__device__ __align__(16) float g_y[NROWS * DIN];           // scan output
__device__ __align__(16) float g_Ap[NCH * NSER];           // [chunk][series]
__device__ __align__(16) float g_Hl[NCH * NSER];
__device__ __align__(16) float g_Hi[NCH * NSER];
__device__ __align__(16) float g_part[128 * DM];
__device__ __align__(16) float g_partsq[128 * DM];
__device__ __align__(16) float g_mean[DM];
__device__ __align__(16) float g_var[DM];

// ---------------- tf32 helpers ----------------
__device__ __forceinline__ uint32_t f2tf32(float x) {
    uint32_t r;
    asm("cvt.rna.tf32.f32 %0, %1;" : "=r"(r) : "f"(x));
    return r;
}

__device__ __forceinline__ void mma_tf32(float c[4],
    uint32_t a0, uint32_t a1, uint32_t a2, uint32_t a3,
    uint32_t b0, uint32_t b1)
{
    asm volatile(
        "mma.sync.aligned.m16n8k8.row.col.f32.tf32.tf32.f32 "
        "{%0,%1,%2,%3}, {%4,%5,%6,%7}, {%8,%9}, {%0,%1,%2,%3};"
        : "+f"(c[0]), "+f"(c[1]), "+f"(c[2]), "+f"(c[3])
        : "r"(a0), "r"(a1), "r"(a2), "r"(a3), "r"(b0), "r"(b1));
}

// ---------------- 3xTF32 tensor-core NT GEMM: C[m,n] = sum_k A[m,k]*W[n,k] ----------------
// 128x64 block tile, BK=16, 8 warps in 4(m) x 2(n), warp tile 32x32 via 2x4 m16n8k8 mma.
// Each operand split hi+lo (tf32); accumulate hi*hi + hi*lo + lo*hi -> ~fp32 accuracy.
// Smem holds fragments in mma-native layout: per-thread A frag = one LDS.128,
// B frag = one LDS.64 (conflict-free).
// A row r at A + (r/rpb)*bsa + (r%rpb)*lda.  epi: 0 none, 1 +bias, 2 softplus(.+bias).
// Requires K % 16 == 0, lda % 4 == 0.
#define TBM 128
#define TBN 64
#define TBK 16
__global__ __launch_bounds__(256) void tc_gemm3(
    const float* __restrict__ A, const float* __restrict__ W,
    const float* __restrict__ bias, float* __restrict__ C,
    int M, int N, int K, int lda, int rpb, long long bsa,
    int ldc, int epi)
{
    // A frag slots: (mgrp[8], ks[2], gid[8], tig[4]) x 4 words = 2048 words (8 KB)
    // W frag slots: (ngrp[8], ks[2], gid[8], tig[4]) x 2 words = 1024 words (4 KB)
    __shared__ __align__(16) uint32_t AsH[2048];
    __shared__ __align__(16) uint32_t AsL[2048];
    __shared__ __align__(16) uint32_t WsH[1024];
    __shared__ __align__(16) uint32_t WsL[1024];

    const int tid = threadIdx.x;
    const int bm = blockIdx.x * TBM, bn = blockIdx.y * TBN;

    // global-load assignments
    const int am0 = tid >> 2;            // 0..63
    const int am1 = am0 + 64;            // 64..127
    const int akq = (tid & 3) * 4;       // k offset within BK
    long long arow0 = -1, arow1 = -1;
    {
        int r0 = bm + am0;
        if (r0 < M) arow0 = (long long)(r0 / rpb) * bsa + (long long)(r0 % rpb) * lda;
        int r1 = bm + am1;
        if (r1 < M) arow1 = (long long)(r1 / rpb) * bsa + (long long)(r1 % rpb) * lda;
    }
    const int wn = tid >> 2;             // 0..63
    const int wkq = (tid & 3) * 4;
    long long wrow = -1;
    if (bn + wn < N) wrow = (long long)(bn + wn) * K;

    const float4 z4 = make_float4(0.f, 0.f, 0.f, 0.f);
    float4 fa0, fa1, fw;
    fa0 = (arow0 >= 0) ? __ldg((const float4*)(A + arow0 + akq)) : z4;
    fa1 = (arow1 >= 0) ? __ldg((const float4*)(A + arow1 + akq)) : z4;
    fw  = (wrow  >= 0) ? __ldg((const float4*)(W + wrow + wkq))  : z4;

    const int wid = tid >> 5, lane = tid & 31;
    const int mgb = (wid & 3) * 2;       // A mgrp base (warp covers mgrp mgb, mgb+1)
    const int ngb = (wid >> 2) * 4;      // W ngrp base (warp covers ngrp ngb..ngb+3)
    const int gid = lane >> 2, tig = lane & 3;

    float acc[2][4][4];
    #pragma unroll
    for (int mt = 0; mt < 2; mt++)
        #pragma unroll
        for (int nt = 0; nt < 4; nt++)
            #pragma unroll
            for (int i = 0; i < 4; i++) acc[mt][nt][i] = 0.f;

    const int nk = K / TBK;
    for (int t = 0; t < nk; t++) {
        __syncthreads();
        // stage A rows am0, am1 (4 k-values each) in fragment layout, hi+lo
        #pragma unroll
        for (int half = 0; half < 2; half++) {
            const int m = half ? am1 : am0;
            const float4 f = half ? fa1 : fa0;
            const int mgrp = m >> 4, sub = (m >> 3) & 1, gr = m & 7;
            const float vv[4] = {f.x, f.y, f.z, f.w};
            #pragma unroll
            for (int j = 0; j < 4; j++) {
                const int k = akq + j;
                const int ks = k >> 3, hk = (k >> 2) & 1, tg = k & 3;
                const int wadr = (((((mgrp * 2 + ks) * 8) + gr) * 4 + tg) << 2) + sub + (hk << 1);
                uint32_t hb = f2tf32(vv[j]);
                AsH[wadr] = hb;
                AsL[wadr] = f2tf32(vv[j] - __uint_as_float(hb));
            }
        }
        // stage W row wn
        {
            const int ngrp = wn >> 3, gr = wn & 7;
            const float vv[4] = {fw.x, fw.y, fw.z, fw.w};
            #pragma unroll
            for (int j = 0; j < 4; j++) {
                const int k = wkq + j;
                const int ks = k >> 3, hk = (k >> 2) & 1, tg = k & 3;
                const int wadr = (((((ngrp * 2 + ks) * 8) + gr) * 4 + tg) << 1) + hk;
                uint32_t hb = f2tf32(vv[j]);
                WsH[wadr] = hb;
                WsL[wadr] = f2tf32(vv[j] - __uint_as_float(hb));
            }
        }
        __syncthreads();

        if (t + 1 < nk) {
            const int k0 = (t + 1) * TBK;
            fa0 = (arow0 >= 0) ? __ldg((const float4*)(A + arow0 + k0 + akq)) : z4;
            fa1 = (arow1 >= 0) ? __ldg((const float4*)(A + arow1 + k0 + akq)) : z4;
            fw  = (wrow  >= 0) ? __ldg((const float4*)(W + wrow + k0 + wkq))  : z4;
        }

        #pragma unroll
        for (int ks = 0; ks < 2; ks++) {
            uint4 ah[2], al[2];
            #pragma unroll
            for (int mt = 0; mt < 2; mt++) {
                const int s = (((mgb + mt) * 2 + ks) * 8 + gid) * 4 + tig;
                ah[mt] = ((const uint4*)AsH)[s];
                al[mt] = ((const uint4*)AsL)[s];
            }
            uint2 bh[4], bl[4];
            #pragma unroll
            for (int nt = 0; nt < 4; nt++) {
                const int s = (((ngb + nt) * 2 + ks) * 8 + gid) * 4 + tig;
                bh[nt] = ((const uint2*)WsH)[s];
                bl[nt] = ((const uint2*)WsL)[s];
            }
            #pragma unroll
            for (int mt = 0; mt < 2; mt++)
                #pragma unroll
                for (int nt = 0; nt < 4; nt++) {
                    mma_tf32(acc[mt][nt], ah[mt].x, ah[mt].y, ah[mt].z, ah[mt].w,
                             bh[nt].x, bh[nt].y);
                    mma_tf32(acc[mt][nt], ah[mt].x, ah[mt].y, ah[mt].z, ah[mt].w,
                             bl[nt].x, bl[nt].y);
                    mma_tf32(acc[mt][nt], al[mt].x, al[mt].y, al[mt].z, al[mt].w,
                             bh[nt].x, bh[nt].y);
                }
        }
    }

    // epilogue
    const int wm  = (wid & 3) * 32;
    const int wnn = (wid >> 2) * 32;
    #pragma unroll
    for (int mt = 0; mt < 2; mt++) {
        #pragma unroll
        for (int nt = 0; nt < 4; nt++) {
            int r0 = bm + wm + mt * 16 + gid;
            int c0 = bn + wnn + nt * 8 + 2 * tig;
            #pragma unroll
            for (int half = 0; half < 2; half++) {
                int r = r0 + half * 8;
                if (r >= M) continue;
                float v0 = acc[mt][nt][half * 2 + 0];
                float v1 = acc[mt][nt][half * 2 + 1];
                if (epi >= 1) {
                    if (c0 < N)     v0 += bias[c0];
                    if (c0 + 1 < N) v1 += bias[c0 + 1];
                }
                if (epi == 2) {
                    v0 = (v0 > 20.f) ? v0 : log1pf(expf(v0));
                    v1 = (v1 > 20.f) ? v1 : log1pf(expf(v1));
                }
                long long base = (long long)r * ldc + c0;
                if (c0 + 1 < N) {
                    *(float2*)&C[base] = make_float2(v0, v1);
                } else if (c0 < N) {
                    C[base] = v0;
                }
            }
        }
    }
}

// ---------------- cls token: u[b,0,:] = x[b,0,:] @ cls_w^T + cls_b + skip ----------------
__global__ void cls_kernel(const float* __restrict__ x, const float* __restrict__ cls_w,
                           const float* __restrict__ cls_b, const float* __restrict__ skip,
                           float* __restrict__ u)
{
    int b = blockIdx.x;
    int m = threadIdx.x;
    __shared__ float xs[DIM];
    for (int i = m; i < DIM; i += 256) xs[i] = x[(long long)b * 1025 * DIM + i];
    __syncthreads();
    float acc = 0.f;
    #pragma unroll 4
    for (int k = 0; k < DIM; k++) acc += xs[k] * cls_w[m * DIM + k];
    long long row = (long long)b * LSEQ;
    u[row * DM + m] = acc + cls_b[m] + skip[row * DM + m];
}

// ---------------- pixel-shuffle + LayerNorm + skip-add ----------------
__global__ void ln_expand_kernel(const float* __restrict__ e, const float* __restrict__ g,
                                 const float* __restrict__ bb, const float* __restrict__ skip,
                                 float* __restrict__ u)
{
    int o = blockIdx.x;                 // [0, 8192)
    int m = threadIdx.x;                // [0, 256)
    int b = o >> 12, rem = o & 4095;
    int t = rem >> 10, ti = rem & 1023;
    int q = ti & 1, w = (ti >> 1) & 15, p = (ti >> 5) & 1, h = ti >> 6;
    int n = h * 16 + w, pq = p * 2 + q;
    long long erow = (long long)((b * 4 + t) * 256 + n);
    float v = e[erow * 1024 + pq * 256 + m];
    __shared__ float red[8];
    float s = v;
    #pragma unroll
    for (int off = 16; off; off >>= 1) s += __shfl_xor_sync(~0u, s, off);
    if ((m & 31) == 0) red[m >> 5] = s;
    __syncthreads();
    float tot = 0.f;
    #pragma unroll
    for (int i = 0; i < 8; i++) tot += red[i];
    float mu = tot * (1.f / 256.f);
    __syncthreads();
    float dv = v - mu;
    s = dv * dv;
    #pragma unroll
    for (int off = 16; off; off >>= 1) s += __shfl_xor_sync(~0u, s, off);
    if ((m & 31) == 0) red[m >> 5] = s;
    __syncthreads();
    tot = 0.f;
    #pragma unroll
    for (int i = 0; i < 8; i++) tot += red[i];
    float var = tot * (1.f / 256.f);
    long long urow = (long long)b * LSEQ + 1 + t * 1024 + ti;
    u[urow * DM + m] = dv * rsqrtf(var + EPSV) * g[m] + bb[m] + skip[urow * DM + m];
}

// ---------------- depthwise causal conv (k=4) + silu ----------------
__global__ void conv_kernel(const float* __restrict__ xz, const float* __restrict__ cw,
                            const float* __restrict__ cb, float* __restrict__ xc)
{
    long long idx = (long long)blockIdx.x * 256 + threadIdx.x;
    if (idx >= (long long)NROWS * DIN) return;
    int d = (int)(idx & 511);
    long long r = idx >> 9;
    int b = (int)(r / LSEQ);
    int l = (int)(r % LSEQ);
    float acc = cb[d];
    #pragma unroll
    for (int k = 0; k < 4; k++) {
        int ls = l - 3 + k;
        if (ls >= 0) acc += cw[d * 4 + k] * xz[((long long)b * LSEQ + ls) * 1024 + d];
    }
    xc[idx] = acc / (1.f + __expf(-acc));
}

// ---------------- chunked scan, pass 1: local scans + decay products ----------------
__global__ void scan1_kernel(const float* __restrict__ delta, const float* __restrict__ xc,
                             const float* __restrict__ dbc, const float* __restrict__ A_log,
                             float* __restrict__ Aprod, float* __restrict__ Hloc)
{
    int gid = blockIdx.x * 16 + (threadIdx.x >> 4);
    int lane = threadIdx.x & 15;
    int d = gid % DIN;
    int rest = gid / DIN;
    int c = rest % NCH;
    int b = rest / NCH;
    float An = -expf(A_log[d * DST + lane]);
    float h = 0.f, ap = 1.f;
    int l0 = c * CHUNK;
    int lend = min(l0 + CHUNK, LSEQ);
    for (int l = l0; l < lend; l++) {
        long long row = (long long)b * LSEQ + l;
        float dl = delta[row * DIN + d];
        float xv = xc[row * DIN + d];
        float Bv = dbc[row * 48 + 16 + lane];
        float a = __expf(dl * An);
        h = h * a + dl * Bv * xv;
        ap *= a;
    }
    long long base = (long long)c * NSER + ((b * DIN + d) * DST + lane);
    Aprod[base] = ap;
    Hloc[base] = h;
}

// ---------------- pass 2: inter-chunk exclusive scan (coalesced) ----------------
__global__ void scan2_kernel(const float* __restrict__ Aprod, const float* __restrict__ Hloc,
                             float* __restrict__ Hinit)
{
    int i = blockIdx.x * 256 + threadIdx.x;
    if (i >= NSER) return;
    float h = 0.f;
    for (int c = 0; c < NCH; c++) {
        long long idx = (long long)c * NSER + i;
        Hinit[idx] = h;
        h = h * Aprod[idx] + Hloc[idx];
    }
}

// ---------------- pass 3: replay + fused output ----------------
__global__ void scan3_kernel(const float* __restrict__ delta, const float* __restrict__ xc,
                             const float* __restrict__ dbc, const float* __restrict__ A_log,
                             const float* __restrict__ Hinit, const float* __restrict__ xz,
                             const float* __restrict__ Dp, float* __restrict__ y)
{
    int gid = blockIdx.x * 16 + (threadIdx.x >> 4);
    int lane = threadIdx.x & 15;
    int d = gid % DIN;
    int rest = gid / DIN;
    int c = rest % NCH;
    int b = rest / NCH;
    float An = -expf(A_log[d * DST + lane]);
    float Dd = Dp[d];
    float h = Hinit[(long long)c * NSER + ((b * DIN + d) * DST + lane)];
    int l0 = c * CHUNK;
    int lend = min(l0 + CHUNK, LSEQ);
    for (int l = l0; l < lend; l++) {
        long long row = (long long)b * LSEQ + l;
        float dl = delta[row * DIN + d];
        float xv = xc[row * DIN + d];
        float Bv = dbc[row * 48 + 16 + lane];
        float Cv = dbc[row * 48 + 32 + lane];
        float a = __expf(dl * An);
        h = h * a + dl * Bv * xv;
        float py = h * Cv;
        py += __shfl_xor_sync(~0u, py, 8, 16);
        py += __shfl_xor_sync(~0u, py, 4, 16);
        py += __shfl_xor_sync(~0u, py, 2, 16);
        py += __shfl_xor_sync(~0u, py, 1, 16);
        if (lane == 0) {
            float z = xz[row * 1024 + 512 + d];
            float sz = z / (1.f + __expf(-z));
            y[row * DIN + d] = (py + xv * Dd) * sz;
        }
    }
}

// ---------------- deterministic batchnorm ----------------
__global__ void bn_part_kernel(const float* __restrict__ u, float* __restrict__ part,
                               float* __restrict__ partsq)
{
    int blk = blockIdx.x;
    int m = threadIdx.x;
    int r0 = blk * 65;
    int r1 = min(r0 + 65, NROWS);
    float s = 0.f, q = 0.f;
    for (int r = r0; r < r1; r++) {
        float v = u[(long long)r * DM + m];
        s += v; q += v * v;
    }
    part[blk * DM + m] = s;
    partsq[blk * DM + m] = q;
}

__global__ void bn_final_kernel(const float* __restrict__ part, const float* __restrict__ partsq,
                                float* __restrict__ mean, float* __restrict__ var)
{
    int m = threadIdx.x;
    float s = 0.f, q = 0.f;
    for (int i = 0; i < 128; i++) { s += part[i * DM + m]; q += partsq[i * DM + m]; }
    float mu = s / (float)NROWS;
    mean[m] = mu;
    var[m] = q / (float)NROWS - mu * mu;
}

__global__ void bn_norm_kernel(const float* __restrict__ u, const float* __restrict__ mean,
                               const float* __restrict__ var, const float* __restrict__ g,
                               const float* __restrict__ bb, float* __restrict__ out,
                               long long out_size)
{
    long long idx = (long long)blockIdx.x * 256 + threadIdx.x;
    if (idx >= out_size) return;
    const long long NEL = (long long)NROWS * DM;
    if (idx < NEL) {
        int m = (int)(idx & 255);
        out[idx] = (u[idx] - mean[m]) * rsqrtf(var[m] + EPSV) * g[m] + bb[m];
    } else {
        out[idx] = 1024.0f;
    }
}

// ---------------- launch ----------------
extern "C" void kernel_launch(void* const* d_in, const int* in_sizes, int n_in,
                              void* d_out, int out_size)
{
    const float* x        = (const float*)d_in[0];
    const float* skip     = (const float*)d_in[1];
    const float* exp_w    = (const float*)d_in[2];
    const float* ln_g     = (const float*)d_in[3];
    const float* ln_b     = (const float*)d_in[4];
    const float* cls_w    = (const float*)d_in[5];
    const float* cls_b    = (const float*)d_in[6];
    const float* in_proj_w= (const float*)d_in[7];
    const float* conv_w   = (const float*)d_in[8];
    const float* conv_b   = (const float*)d_in[9];
    const float* xproj_w  = (const float*)d_in[10];
    const float* dt_w     = (const float*)d_in[11];
    const float* dt_b     = (const float*)d_in[12];
    const float* A_log    = (const float*)d_in[13];
    const float* Dp       = (const float*)d_in[14];
    const float* out_w    = (const float*)d_in[15];
    const float* bn_g     = (const float*)d_in[16];
    const float* bn_b     = (const float*)d_in[17];
    float* out = (float*)d_out;

    float *pe, *pu, *pu2, *pxz, *pxc, *pdbc, *pdelta, *py, *pAp, *pHl, *pHi;
    float *ppart, *ppartsq, *pmean, *pvar;
    cudaGetSymbolAddress((void**)&pe, g_e);
    cudaGetSymbolAddress((void**)&pu, g_u);
    cudaGetSymbolAddress((void**)&pu2, g_u2);
    cudaGetSymbolAddress((void**)&pxz, g_xz);
    cudaGetSymbolAddress((void**)&pxc, g_xc);
    cudaGetSymbolAddress((void**)&pdbc, g_dbc);
    cudaGetSymbolAddress((void**)&pdelta, g_delta);
    cudaGetSymbolAddress((void**)&py, g_y);
    cudaGetSymbolAddress((void**)&pAp, g_Ap);
    cudaGetSymbolAddress((void**)&pHl, g_Hl);
    cudaGetSymbolAddress((void**)&pHi, g_Hi);
    cudaGetSymbolAddress((void**)&ppart, g_part);
    cudaGetSymbolAddress((void**)&ppartsq, g_partsq);
    cudaGetSymbolAddress((void**)&pmean, g_mean);
    cudaGetSymbolAddress((void**)&pvar, g_var);

    // 1. cls token rows
    cls_kernel<<<2, 256>>>(x, cls_w, cls_b, skip, pu);

    // 2. expand GEMM (3xtf32): (2048,512) x (1024,512)^T -> g_e
    tc_gemm3<<<dim3(16, 16), 256>>>(x + 512, exp_w, nullptr, pe,
                                    2048, 1024, 512, 512, 1024, (long long)1025 * 512, 1024, 0);

    // 3. pixel-shuffle + LN + skip
    ln_expand_kernel<<<8192, 256>>>(pe, ln_g, ln_b, skip, pu);

    float* uin = pu;
    float* uout = pu2;
    const int HUGE_RPB = 1 << 30;
    for (int layer = 0; layer < 2; layer++) {
        const float* Alog_l = A_log + (size_t)layer * DIN * DST;
        // in_proj (3xtf32): (8194,256) x (1024,256)^T -> xz
        tc_gemm3<<<dim3(65, 16), 256>>>(uin, in_proj_w + (size_t)layer * 1024 * DM, nullptr, pxz,
                                        NROWS, 1024, DM, DM, HUGE_RPB, 0, 1024, 0);
        // depthwise conv + silu
        conv_kernel<<<16388, 256>>>(pxz, conv_w + (size_t)layer * DIN * 4,
                                    conv_b + (size_t)layer * DIN, pxc);
        // x_proj (3xtf32): (8194,512) x (48,512)^T -> dbc
        tc_gemm3<<<dim3(65, 1), 256>>>(pxc, xproj_w + (size_t)layer * 48 * DIN, nullptr, pdbc,
                                       NROWS, 48, DIN, DIN, HUGE_RPB, 0, 48, 0);
        // delta (3xtf32): softplus(dt @ Wdt^T + bdt): (8194,16) x (512,16)^T
        tc_gemm3<<<dim3(65, 8), 256>>>(pdbc, dt_w + (size_t)layer * DIN * DTR,
                                       dt_b + (size_t)layer * DIN, pdelta,
                                       NROWS, DIN, DTR, 48, HUGE_RPB, 0, DIN, 2);
        // chunked selective scan
        scan1_kernel<<<4160, 256>>>(pdelta, pxc, pdbc, Alog_l, pAp, pHl);
        scan2_kernel<<<64, 256>>>(pAp, pHl, pHi);
        scan3_kernel<<<4160, 256>>>(pdelta, pxc, pdbc, Alog_l, pHi, pxz,
                                    Dp + (size_t)layer * DIN, py);
        // out_proj (3xtf32): (8194,512) x (256,512)^T -> uout
        tc_gemm3<<<dim3(65, 4), 256>>>(py, out_w + (size_t)layer * DM * DIN, nullptr, uout,
                                       NROWS, DM, DIN, DIN, HUGE_RPB, 0, DM, 0);
        float* tmp = uin; uin = uout; uout = tmp;
    }

    // batchnorm (deterministic two-stage reduction)
    bn_part_kernel<<<128, 256>>>(uin, ppart, ppartsq);
    bn_final_kernel<<<1, 256>>>(ppart, ppartsq, pmean, pvar);
    long long nb = ((long long)out_size + 255) / 256;
    bn_norm_kernel<<<(int)nb, 256>>>(uin, pmean, pvar, bn_g, bn_b, out, (long long)out_size);
}